// round 2
// baseline (speedup 1.0000x reference)
#include <cuda_runtime.h>
#include <math.h>

#define NB 256      // batch size B
#define NE 8192     // epoch size E
#define NC 19       // classes C
#define SPLIT 8     // E-dim splits in K2 -> 19*8 = 152 blocks ~ 148 SMs
#define CHUNK (NE / SPLIT)        // 1024
#define ITERS (CHUNK / NB)        // 4
#define NBLK (NC * SPLIT)         // 152

// ---------------- scratch (device globals; no allocations) ----------------
__device__ float d_posS[NC][NB];        // sorted ascending positive yp (first np valid)
__device__ float d_negS[NC][NB];        // sorted ascending negative yp (first nn valid)
__device__ float d_P1[NC][NB + 1];      // exclusive prefix sums of pos values
__device__ float d_P2[NC][NB + 1];      // ... of pos squares
__device__ float d_N1[NC][NB + 1];      // ... of neg values
__device__ float d_N2[NC][NB + 1];      // ... of neg squares
__device__ int   d_np[NC];              // positives in current batch
__device__ int   d_cap[NC];             // positives in epoch (cap_pos count)
__device__ float d_pm2[NC][SPLIT];      // per-block partial m2
__device__ float d_pm3[NC][SPLIT];      // per-block partial m3
__device__ unsigned int d_done;         // finalize counter (reset by last block)

// inclusive Hillis-Steele scan over NB elems; store exclusive prefix [0..NB] to global
__device__ __forceinline__ void scan_store(float* s_scan, float val, float* gdst, int t) {
    s_scan[t] = val;
    __syncthreads();
#pragma unroll
    for (int off = 1; off < NB; off <<= 1) {
        float v = (t >= off) ? s_scan[t - off] : 0.0f;
        __syncthreads();
        s_scan[t] += v;
        __syncthreads();
    }
    gdst[t + 1] = s_scan[t];
    if (t == 0) gdst[0] = 0.0f;
    __syncthreads();
}

// ---------------- K1: per-class sort + prefix sums + epoch-pos count -------
__global__ void k1_setup(const float* __restrict__ y_pred,
                         const float* __restrict__ y_true,
                         const float* __restrict__ epoch_true) {
    const int c = blockIdx.x;
    const int t = threadIdx.x;

    __shared__ float s_yp[NB];
    __shared__ unsigned char s_fl[NB];
    __shared__ float s_pos[NB];
    __shared__ float s_neg[NB];
    __shared__ float s_scan[NB];
    __shared__ int   s_ired[NB];

    const float yp = y_pred[t * NC + c];
    const int isp = (y_true[t * NC + c] >= 0.5f) ? 1 : 0;
    s_yp[t] = yp;
    s_fl[t] = (unsigned char)isp;
    s_pos[t] = 0.0f;
    s_neg[t] = 0.0f;

    // kick off the epoch-positive count loads early (independent of sort)
    int cnt = 0;
#pragma unroll 8
    for (int j = t; j < NE; j += NB)
        cnt += (epoch_true[j * NC + c] >= 0.5f) ? 1 : 0;

    __syncthreads();

    // rank within my group (stable on ties via index), count batch positives
    int rank = 0, np = 0;
#pragma unroll 8
    for (int i = 0; i < NB; ++i) {
        const int fi = (int)s_fl[i];
        const float v = s_yp[i];
        np += fi;
        if (fi == isp && (v < yp || (v == yp && i < t))) rank++;
    }
    __syncthreads();
    if (isp) s_pos[rank] = yp; else s_neg[rank] = yp;
    __syncthreads();

    d_posS[c][t] = s_pos[t];
    d_negS[c][t] = s_neg[t];

    const float pv = s_pos[t], nv = s_neg[t];
    scan_store(s_scan, pv,      d_P1[c], t);
    scan_store(s_scan, pv * pv, d_P2[c], t);
    scan_store(s_scan, nv,      d_N1[c], t);
    scan_store(s_scan, nv * nv, d_N2[c], t);

    s_ired[t] = cnt;
    __syncthreads();
#pragma unroll
    for (int o = NB / 2; o > 0; o >>= 1) {
        if (t < o) s_ired[t] += s_ired[t + o];
        __syncthreads();
    }
    if (t == 0) {
        d_cap[c] = s_ired[0];
        d_np[c]  = np;
    }
}

// ---------------- K2: epoch pass (closed form + binary search) + finalize --
__global__ void k2_main(const float* __restrict__ epoch_pred,
                        const float* __restrict__ epoch_true,
                        const float* __restrict__ rand_pos,
                        const float* __restrict__ rand_neg,
                        const float* __restrict__ gamma,
                        float* __restrict__ out) {
    const int c = blockIdx.x;
    const int s = blockIdx.y;
    const int t = threadIdx.x;

    __shared__ float sp[NB], sn[NB];
    __shared__ float p1[NB + 1], p2[NB + 1], n1[NB + 1], n2[NB + 1];
    __shared__ float red[NB];
    __shared__ unsigned int s_rank;

    sp[t] = d_posS[c][t];
    sn[t] = d_negS[c][t];
    p1[t] = d_P1[c][t];
    p2[t] = d_P2[c][t];
    n1[t] = d_N1[c][t];
    n2[t] = d_N2[c][t];
    if (t == 0) {
        p1[NB] = d_P1[c][NB];
        p2[NB] = d_P2[c][NB];
        n1[NB] = d_N1[c][NB];
        n2[NB] = d_N2[c][NB];
    }
    __syncthreads();

    const int np = d_np[c];
    const int nn = NB - np;
    const float p = 1000.0f / fmaxf((float)d_cap[c], 1.0f);
    const float g = gamma[c];
    const float nTot1 = n1[nn];
    const float nTot2 = n2[nn];

    float m2 = 0.0f, m3 = 0.0f;

    const int jbase = s * CHUNK + t;
#pragma unroll
    for (int k = 0; k < ITERS; ++k) {
        const int j = jbase + k * NB;
        const float et = epoch_true[j * NC + c];
        if (et >= 0.5f) {
            if (rand_pos[j * NC + c] < p) {
                const float tt = epoch_pred[j * NC + c] - g;
                // first index with sn[idx] > tt (ties contribute 0 either way)
                int lo = 0, hi = nn;
                while (lo < hi) {
                    const int mid = (lo + hi) >> 1;
                    if (sn[mid] <= tt) lo = mid + 1; else hi = mid;
                }
                const float cntf = (float)(nn - lo);
                const float S1 = nTot1 - n1[lo];
                const float S2 = nTot2 - n2[lo];
                // sum (v - tt)^2 over suffix = S2 - 2*tt*S1 + cnt*tt^2
                m3 += fmaf(fmaf(cntf, tt, -2.0f * S1), tt, S2);
            }
        } else {
            if (rand_neg[j * NC + c] < p) {
                const float x = epoch_pred[j * NC + c] + g;
                // count of pos values < x (ties contribute 0)
                int lo = 0, hi = np;
                while (lo < hi) {
                    const int mid = (lo + hi) >> 1;
                    if (sp[mid] < x) lo = mid + 1; else hi = mid;
                }
                const float kk = (float)lo;
                // sum (x - v)^2 over prefix = kk*x^2 - 2*x*P1 + P2
                m2 += fmaf(fmaf(kk, x, -2.0f * p1[lo]), x, p2[lo]);
            }
        }
    }

    // block reduce m2, m3
    red[t] = m2;
    __syncthreads();
#pragma unroll
    for (int o = NB / 2; o > 0; o >>= 1) {
        if (t < o) red[t] += red[t + o];
        __syncthreads();
    }
    const float bm2 = red[0];
    __syncthreads();

    red[t] = m3;
    __syncthreads();
#pragma unroll
    for (int o = NB / 2; o > 0; o >>= 1) {
        if (t < o) red[t] += red[t + o];
        __syncthreads();
    }

    if (t == 0) {
        d_pm2[c][s] = bm2;
        d_pm3[c][s] = red[0];
        __threadfence();
        s_rank = atomicAdd(&d_done, 1u);
    }
    __syncthreads();

    // ------- last block finalizes -------
    if (s_rank == NBLK - 1) {
        if (t < NC) {
            float res;
            const int cnp = d_np[t];
            if (cnp == 0 || cnp == NB) {
                // degenerate: sum(yp) * 1e-8
                res = (d_P1[t][NB] + d_N1[t][NB]) * 1e-8f;
            } else {
                float am2 = 0.0f, am3 = 0.0f;
#pragma unroll
                for (int q = 0; q < SPLIT; ++q) {
                    am2 += d_pm2[t][q];
                    am3 += d_pm3[t][q];
                }
                res = am2 * 1e-3f + am3 * 1e-3f;
                if (isnan(res)) res = 0.0f;
            }
            red[t] = res;
        }
        __syncthreads();
        if (t == 0) {
            float acc = 0.0f;
#pragma unroll
            for (int q = 0; q < NC; ++q) acc += red[q];
            out[0] = acc / (float)NC;
            d_done = 0;  // reset for next graph replay (deterministic)
        }
    }
}

// ---------------- launch ----------------------------------------------------
extern "C" void kernel_launch(void* const* d_in, const int* in_sizes, int n_in,
                              void* d_out, int out_size) {
    const float* y_pred     = (const float*)d_in[0];
    const float* y_true     = (const float*)d_in[1];
    const float* epoch_pred = (const float*)d_in[2];
    const float* epoch_true = (const float*)d_in[3];
    const float* gamma      = (const float*)d_in[4];
    const float* rand_pos   = (const float*)d_in[5];
    const float* rand_neg   = (const float*)d_in[6];
    (void)in_sizes; (void)n_in; (void)out_size;

    k1_setup<<<NC, NB>>>(y_pred, y_true, epoch_true);
    dim3 g2(NC, SPLIT);
    k2_main<<<g2, NB>>>(epoch_pred, epoch_true, rand_pos, rand_neg, gamma,
                        (float*)d_out);
}

// round 6
// speedup vs baseline: 1.3135x; 1.3135x over previous
#include <cuda_runtime.h>
#include <math.h>

#define NB 256      // batch size B
#define NE 8192     // epoch size E
#define NC 19       // classes C
#define NPAIR ((NC + 1) / 2)      // 10 class pairs (last is a singleton)

#define SPLIT 32                  // E-dim splits in K2
#define CHUNK (NE / SPLIT)        // 256 == NB (one epoch row per thread)
#define NBLK (NPAIR * SPLIT)      // 320 blocks in K2

#define CSPLIT 8                  // E-dim splits for cap count in K1
#define CCHUNK (NE / CSPLIT)      // 1024
#define CITERS (CCHUNK / NB)      // 4

// ---------------- scratch (device globals; no allocations) ----------------
__device__ float d_posS[NC][NB];        // sorted ascending positive yp (first np valid)
__device__ float d_negS[NC][NB];        // sorted ascending negative yp (first nn valid)
__device__ float d_P1[NC][NB + 1];      // exclusive prefix sums of pos values
__device__ float d_P2[NC][NB + 1];      // ... of pos squares
__device__ float d_N1[NC][NB + 1];      // ... of neg values
__device__ float d_N2[NC][NB + 1];      // ... of neg squares
__device__ int   d_np[NC];              // positives in current batch
__device__ int   d_capPart[NC][CSPLIT]; // partial epoch-positive counts
__device__ float d_pm2[NC][SPLIT];      // per-(class,split) partial m2
__device__ float d_pm3[NC][SPLIT];      // per-(class,split) partial m3
__device__ unsigned int d_done;         // finalize counter (zero-init; reset by last block)

// block-wide inclusive scan (256 threads) via warp shuffles
__device__ __forceinline__ float block_scan_incl(float v, int t, float* s_w) {
    const int lane = t & 31, wid = t >> 5;
#pragma unroll
    for (int o = 1; o < 32; o <<= 1) {
        const float u = __shfl_up_sync(0xffffffffu, v, o);
        if (lane >= o) v += u;
    }
    if (lane == 31) s_w[wid] = v;
    __syncthreads();
    if (wid == 0) {
        float w = (lane < 8) ? s_w[lane] : 0.0f;
#pragma unroll
        for (int o = 1; o < 8; o <<= 1) {
            const float u = __shfl_up_sync(0xffffffffu, w, o);
            if (lane >= o) w += u;
        }
        if (lane < 8) s_w[lane] = w;
    }
    __syncthreads();
    const float res = v + ((wid > 0) ? s_w[wid - 1] : 0.0f);
    __syncthreads();   // s_w reused by next scan
    return res;
}

__device__ __forceinline__ void scan_store(float val, float* gdst, int t, float* s_w) {
    const float incl = block_scan_incl(val, t, s_w);
    gdst[t + 1] = incl;
    if (t == 0) gdst[0] = 0.0f;
}

// ---------------- K1: grid (NC, CSPLIT+1) ----------------------------------
// blockIdx.y <  CSPLIT : even c only — paired epoch-positive count (c, c+1)
// blockIdx.y == CSPLIT : per-class sort of the 256 batch preds + prefix sums
__global__ void __launch_bounds__(NB)
k1_setup(const float* __restrict__ y_pred,
         const float* __restrict__ y_true,
         const float* __restrict__ epoch_true) {
    const int c = blockIdx.x;
    const int y = blockIdx.y;
    const int t = threadIdx.x;
    const int lane = t & 31, wid = t >> 5;

    if (y < CSPLIT) {
        if (c & 1) return;                 // pairs handled by even-c blocks
        const bool has2 = (c + 1) < NC;
        int cnt0 = 0, cnt1 = 0;
        const int jbase = y * CCHUNK + t;
#pragma unroll
        for (int k = 0; k < CITERS; ++k) {
            const int base = (jbase + k * NB) * NC + c;
            const float e0 = epoch_true[base];
            const float e1 = has2 ? epoch_true[base + 1] : 0.0f;  // same sector
            cnt0 += (e0 >= 0.5f);
            cnt1 += (e1 >= 0.5f);
        }
#pragma unroll
        for (int o = 16; o > 0; o >>= 1) {
            cnt0 += __shfl_down_sync(0xffffffffu, cnt0, o);
            cnt1 += __shfl_down_sync(0xffffffffu, cnt1, o);
        }
        __shared__ int s_c0[8], s_c1[8];
        if (lane == 0) { s_c0[wid] = cnt0; s_c1[wid] = cnt1; }
        __syncthreads();
        if (t == 0) {
            int t0 = 0, t1 = 0;
#pragma unroll
            for (int i = 0; i < 8; ++i) { t0 += s_c0[i]; t1 += s_c1[i]; }
            d_capPart[c][y] = t0;
            if (has2) d_capPart[c + 1][y] = t1;
        }
        return;
    }

    // ---- sort + prefix sums (one block per class) ----
    __shared__ float s_yp[NB];
    __shared__ unsigned char s_fl[NB];
    __shared__ float s_pos[NB];
    __shared__ float s_neg[NB];
    __shared__ float s_w[8];

    const float yp = y_pred[t * NC + c];
    const int isp = (y_true[t * NC + c] >= 0.5f) ? 1 : 0;
    s_yp[t] = yp;
    s_fl[t] = (unsigned char)isp;
    s_pos[t] = 0.0f;
    s_neg[t] = 0.0f;
    __syncthreads();

    // rank within my group (stable on ties via index), count batch positives
    int rank = 0, np = 0;
#pragma unroll 8
    for (int i = 0; i < NB; ++i) {
        const int fi = (int)s_fl[i];
        const float v = s_yp[i];
        np += fi;
        if (fi == isp && (v < yp || (v == yp && i < t))) rank++;
    }
    __syncthreads();
    if (isp) s_pos[rank] = yp; else s_neg[rank] = yp;
    __syncthreads();

    const float pv = s_pos[t], nv = s_neg[t];
    d_posS[c][t] = pv;
    d_negS[c][t] = nv;

    scan_store(pv,      d_P1[c], t, s_w);
    scan_store(pv * pv, d_P2[c], t, s_w);
    scan_store(nv,      d_N1[c], t, s_w);
    scan_store(nv * nv, d_N2[c], t, s_w);

    if (t == 0) d_np[c] = np;
}

// ---------------- K2: epoch pass over a CLASS PAIR + finalize ---------------
__global__ void __launch_bounds__(NB)
k2_main(const float* __restrict__ epoch_pred,
        const float* __restrict__ epoch_true,
        const float* __restrict__ rand_pos,
        const float* __restrict__ rand_neg,
        const float* __restrict__ gamma,
        float* __restrict__ out) {
    const int c0 = 2 * blockIdx.x;
    const int s  = blockIdx.y;
    const int t  = threadIdx.x;
    const int lane = t & 31, wid = t >> 5;
    const bool has2 = (c0 + 1) < NC;
    const int c1 = has2 ? (c0 + 1) : c0;   // clamped (outputs guarded)

    __shared__ float sp[2][NB], sn[2][NB];
    __shared__ float p1[2][NB + 1], p2[2][NB + 1], n1[2][NB + 1], n2[2][NB + 1];
    __shared__ float s_p[2], s_g[2];
    __shared__ int   s_np[2];
    __shared__ float s_r[4][8];
    __shared__ float s_fin[32];
    __shared__ unsigned int s_rank;

    // ---- issue ALL epoch-side global loads up-front (8-wide MLP; class
    //      pair shares sectors, so warp sector count == single-class case) --
    const int idx0 = (s * CHUNK + t) * NC + c0;
    const float et0 = epoch_true[idx0];
    const float rp0 = rand_pos[idx0];
    const float rn0 = rand_neg[idx0];
    const float ep0 = epoch_pred[idx0];
    const float et1 = epoch_true[idx0 + 1 - (has2 ? 0 : 1)];
    const float rp1 = rand_pos[idx0 + 1 - (has2 ? 0 : 1)];
    const float rn1 = rand_neg[idx0 + 1 - (has2 ? 0 : 1)];
    const float ep1 = epoch_pred[idx0 + 1 - (has2 ? 0 : 1)];

    // ---- per-block scalars (cap, gamma, np) by threads 0/1 ----
    if (t < 2) {
        const int cc = (t == 0) ? c0 : c1;
        int cap = 0;
#pragma unroll
        for (int q = 0; q < CSPLIT; ++q) cap += d_capPart[cc][q];
        s_p[t]  = 1000.0f / fmaxf((float)cap, 1.0f);
        s_g[t]  = gamma[cc];
        s_np[t] = d_np[cc];
    }

    // ---- table fill for both classes ----
    sp[0][t] = d_posS[c0][t];  sp[1][t] = d_posS[c1][t];
    sn[0][t] = d_negS[c0][t];  sn[1][t] = d_negS[c1][t];
    p1[0][t] = d_P1[c0][t];    p1[1][t] = d_P1[c1][t];
    p2[0][t] = d_P2[c0][t];    p2[1][t] = d_P2[c1][t];
    n1[0][t] = d_N1[c0][t];    n1[1][t] = d_N1[c1][t];
    n2[0][t] = d_N2[c0][t];    n2[1][t] = d_N2[c1][t];
    if (t == 0) {
#pragma unroll
        for (int k = 0; k < 2; ++k) {
            const int cc = k ? c1 : c0;
            p1[k][NB] = d_P1[cc][NB];
            p2[k][NB] = d_P2[cc][NB];
            n1[k][NB] = d_N1[cc][NB];
            n2[k][NB] = d_N2[cc][NB];
        }
    }
    __syncthreads();

    float m2[2] = {0.0f, 0.0f}, m3[2] = {0.0f, 0.0f};

#pragma unroll
    for (int k = 0; k < 2; ++k) {
        const float et = k ? et1 : et0;
        const float rp = k ? rp1 : rp0;
        const float rn = k ? rn1 : rn0;
        const float ep = k ? ep1 : ep0;
        const int np = s_np[k];
        const int nn = NB - np;

        const bool isPos = et >= 0.5f;
        const float r = isPos ? rp : rn;
        if (r < s_p[k]) {
            const float g = s_g[k];
            const float key = isPos ? (ep - g) : (ep + g);
            const float* arr = isPos ? sn[k] : sp[k];
            const int n = isPos ? nn : np;
            int lo = 0, hi = n;
            while (lo < hi) {
                const int mid = (lo + hi) >> 1;
                const float v = arr[mid];
                const bool goR = isPos ? (v <= key) : (v < key);
                if (goR) lo = mid + 1; else hi = mid;
            }
            if (isPos) {
                // sum over batch negatives > key of (v - key)^2
                const float cntf = (float)(nn - lo);
                const float S1 = n1[k][nn] - n1[k][lo];
                const float S2 = n2[k][nn] - n2[k][lo];
                m3[k] = fmaf(fmaf(cntf, key, -2.0f * S1), key, S2);
            } else {
                // sum over batch positives < key of (key - v)^2
                const float kk = (float)lo;
                m2[k] = fmaf(fmaf(kk, key, -2.0f * p1[k][lo]), key, p2[k][lo]);
            }
        }
    }

    // ---- warp-shuffle reduce (4 accumulators), then 8-way ----
#pragma unroll
    for (int o = 16; o > 0; o >>= 1) {
        m2[0] += __shfl_down_sync(0xffffffffu, m2[0], o);
        m3[0] += __shfl_down_sync(0xffffffffu, m3[0], o);
        m2[1] += __shfl_down_sync(0xffffffffu, m2[1], o);
        m3[1] += __shfl_down_sync(0xffffffffu, m3[1], o);
    }
    if (lane == 0) {
        s_r[0][wid] = m2[0];
        s_r[1][wid] = m3[0];
        s_r[2][wid] = m2[1];
        s_r[3][wid] = m3[1];
    }
    __syncthreads();

    if (t == 0) {
        float a0 = 0.0f, a1 = 0.0f, a2 = 0.0f, a3 = 0.0f;
#pragma unroll
        for (int i = 0; i < 8; ++i) {
            a0 += s_r[0][i]; a1 += s_r[1][i];
            a2 += s_r[2][i]; a3 += s_r[3][i];
        }
        d_pm2[c0][s] = a0;
        d_pm3[c0][s] = a1;
        if (has2) {
            d_pm2[c0 + 1][s] = a2;
            d_pm3[c0 + 1][s] = a3;
        }
        __threadfence();
        s_rank = atomicAdd(&d_done, 1u);
    }
    __syncthreads();

    // ------- last block finalizes -------
    if (s_rank == NBLK - 1) {
        if (t < NC) {
            float res;
            const int cnp = d_np[t];
            if (cnp == 0 || cnp == NB) {
                res = (d_P1[t][NB] + d_N1[t][NB]) * 1e-8f;  // sum(yp) * 1e-8
            } else {
                float am2 = 0.0f, am3 = 0.0f;
#pragma unroll
                for (int q = 0; q < SPLIT; ++q) {
                    am2 += d_pm2[t][q];
                    am3 += d_pm3[t][q];
                }
                res = am2 * 1e-3f + am3 * 1e-3f;
                if (isnan(res)) res = 0.0f;
            }
            s_fin[t] = res;
        }
        __syncthreads();
        if (t == 0) {
            float acc = 0.0f;
#pragma unroll
            for (int q = 0; q < NC; ++q) acc += s_fin[q];
            out[0] = acc / (float)NC;
            d_done = 0;  // reset for next graph replay (deterministic)
        }
    }
}

// ---------------- launch ----------------------------------------------------
extern "C" void kernel_launch(void* const* d_in, const int* in_sizes, int n_in,
                              void* d_out, int out_size) {
    const float* y_pred     = (const float*)d_in[0];
    const float* y_true     = (const float*)d_in[1];
    const float* epoch_pred = (const float*)d_in[2];
    const float* epoch_true = (const float*)d_in[3];
    const float* gamma      = (const float*)d_in[4];
    const float* rand_pos   = (const float*)d_in[5];
    const float* rand_neg   = (const float*)d_in[6];
    (void)in_sizes; (void)n_in; (void)out_size;

    dim3 g1(NC, CSPLIT + 1);
    k1_setup<<<g1, NB>>>(y_pred, y_true, epoch_true);
    dim3 g2(NPAIR, SPLIT);
    k2_main<<<g2, NB>>>(epoch_pred, epoch_true, rand_pos, rand_neg, gamma,
                        (float*)d_out);
}